// round 5
// baseline (speedup 1.0000x reference)
#include <cuda_runtime.h>
#include <cuda_fp16.h>
#include <cstdint>

#define HH 1024
#define WW 1024
#define XV 8      // output pixels per thread in x (two float4 stores)
#define RWS 16    // output rows per thread strip

// One converted input row over the 12-float window v = cols x0-2 .. x0+9:
// h[0..5]  = aligned pairs  (v[2m],   v[2m+1])   m=0..5
// h[6..10] = shifted pairs  (v[2m+1], v[2m+2])   m=0..4
struct RowH {
    __half2 h[11];
};

__device__ __forceinline__ void load_row(RowH& R, const float* __restrict__ ip,
                                         int y, int x0, bool interior) {
    float v[12];
    const float INFv = __int_as_float(0x7f800000);
    if (y < 0 || y >= HH) {
#pragma unroll
        for (int m = 0; m < 12; ++m) v[m] = INFv;
    } else if (interior) {
        const float* base = ip + (size_t)y * WW + x0;
        float2 p0 = *reinterpret_cast<const float2*>(base - 2);   // 8B aligned
        float4 p1 = *reinterpret_cast<const float4*>(base);       // 32B aligned
        float4 p2 = *reinterpret_cast<const float4*>(base + 4);
        float2 p3 = *reinterpret_cast<const float2*>(base + 8);
        v[0] = p0.x;  v[1] = p0.y;
        v[2] = p1.x;  v[3] = p1.y;  v[4] = p1.z;  v[5] = p1.w;
        v[6] = p2.x;  v[7] = p2.y;  v[8] = p2.z;  v[9] = p2.w;
        v[10] = p3.x; v[11] = p3.y;
    } else {
        const float* base = ip + (size_t)y * WW;
#pragma unroll
        for (int m = 0; m < 12; ++m) {
            int col = x0 - 2 + m;
            v[m] = (col >= 0 && col < WW) ? base[col] : INFv;
        }
    }
#pragma unroll
    for (int m = 0; m < 6; ++m) R.h[m] = __floats2half2_rn(v[2 * m], v[2 * m + 1]);
#pragma unroll
    for (int m = 0; m < 5; ++m) R.h[6 + m] = __floats2half2_rn(v[2 * m + 1], v[2 * m + 2]);
}

__global__ __launch_bounds__(128, 6)
void erosion5x5_h2x8_kernel(const float* __restrict__ img,
                            const float* __restrict__ filt,
                            float* __restrict__ out) {
    __shared__ __half2 sfilt[25];
    if (threadIdx.x < 25)
        sfilt[threadIdx.x] = __float2half2_rn(filt[threadIdx.x]);
    __syncthreads();

    const int x0 = (blockIdx.x * blockDim.x + threadIdx.x) * XV;
    const int y0 = blockIdx.y * RWS;
    const size_t plane = (size_t)blockIdx.z * (size_t)HH * (size_t)WW;
    const float* ip = img + plane;
    float* op = out + plane;

    const bool interior = (x0 >= 2) && (x0 + 10 <= WW);

    // Rolling 5-row ring: slot k%5 holds input row y0+k-2 (full unroll -> static)
    RowH W[5];
#pragma unroll
    for (int k = 0; k < 4; ++k)
        load_row(W[k], ip, y0 + k - 2, x0, interior);

#pragma unroll
    for (int r = 0; r < RWS; ++r) {
        // Fresh row feeds tap rows i=4 (consumed last) -> maximal latency slack
        load_row(W[(r + 4) % 5], ip, y0 + r + 2, x0, interior);

        // 4 packed accumulators = 4 independent min-chains (pixel pairs 01,23,45,67)
        __half2 a[4];
        {
            const RowH& R0 = W[r % 5];
            const __half2 f0 = sfilt[0];
#pragma unroll
            for (int p = 0; p < 4; ++p)          // tap (0,0): idx c+j = 2p, even
                a[p] = __hsub2(R0.h[p], f0);
        }
#pragma unroll
        for (int i = 0; i < 5; ++i) {
            const RowH& R = W[(r + i) % 5];
#pragma unroll
            for (int j = 0; j < 5; ++j) {
                if (i == 0 && j == 0) continue;
                const __half2 f = sfilt[i * 5 + j];   // LDS.32 broadcast
#pragma unroll
                for (int p = 0; p < 4; ++p) {
                    const int idx = 2 * p + j;        // window col pair start
                    const __half2 x = ((idx & 1) == 0) ? R.h[idx / 2]
                                                       : R.h[6 + (idx - 1) / 2];
                    a[p] = __hmin2(a[p], __hsub2(x, f));
                }
            }
        }

        float2 l0 = __half22float2(a[0]);
        float2 l1 = __half22float2(a[1]);
        float2 l2 = __half22float2(a[2]);
        float2 l3 = __half22float2(a[3]);
        float* obase = op + (size_t)(y0 + r) * WW + x0;
        *reinterpret_cast<float4*>(obase)     = make_float4(l0.x, l0.y, l1.x, l1.y);
        *reinterpret_cast<float4*>(obase + 4) = make_float4(l2.x, l2.y, l3.x, l3.y);
    }
}

extern "C" void kernel_launch(void* const* d_in, const int* in_sizes, int n_in,
                              void* d_out, int out_size) {
    const float* image = (const float*)d_in[0];
    const float* filt  = (const float*)d_in[1];
    float* out = (float*)d_out;

    const int planes = in_sizes[0] / (HH * WW);  // 32*3 = 96

    dim3 block(128, 1, 1);
    dim3 grid(WW / (128 * XV), HH / RWS, planes);  // (1, 64, 96)
    erosion5x5_h2x8_kernel<<<grid, block>>>(image, filt, out);
}

// round 6
// speedup vs baseline: 1.1477x; 1.1477x over previous
#include <cuda_runtime.h>
#include <cstdint>

#define HH 1024
#define WW 1024
#define XV 4      // output pixels per thread (one float4 store)
#define RWS 16    // output rows per thread strip

// Load 8-float window v = input cols x0-2 .. x0+5 of row y (inf-padded).
__device__ __forceinline__ void load_row8(float* v, const float* __restrict__ ip,
                                          int y, int x0, bool interior) {
    const float INFv = __int_as_float(0x7f800000);
    if (y < 0 || y >= HH) {
#pragma unroll
        for (int m = 0; m < 8; ++m) v[m] = INFv;
    } else if (interior) {
        const float* base = ip + (size_t)y * WW + x0;
        float2 p0 = *reinterpret_cast<const float2*>(base - 2);  // 8B aligned
        float4 p1 = *reinterpret_cast<const float4*>(base);      // 16B aligned
        float2 p2 = *reinterpret_cast<const float2*>(base + 4);
        v[0] = p0.x; v[1] = p0.y;
        v[2] = p1.x; v[3] = p1.y; v[4] = p1.z; v[5] = p1.w;
        v[6] = p2.x; v[7] = p2.y;
    } else {
        const float* base = ip + (size_t)y * WW;
#pragma unroll
        for (int m = 0; m < 8; ++m) {
            int col = x0 - 2 + m;
            v[m] = (col >= 0 && col < WW) ? base[col] : INFv;
        }
    }
}

__global__ __launch_bounds__(128, 8)
void erosion5x5_f32v2_kernel(const float* __restrict__ img,
                             const float* __restrict__ filt,
                             float* __restrict__ out) {
    const int x0 = (blockIdx.x * blockDim.x + threadIdx.x) * XV;
    const int y0 = blockIdx.y * RWS;
    const size_t plane = (size_t)blockIdx.z * (size_t)HH * (size_t)WW;
    const float* ip = img + plane;
    float* op = out + plane;

    const bool interior = (x0 >= 2) && (x0 + 6 <= WW);

    // Filter into registers; ptxas may rematerialize as L1-hit LDG under the
    // 64-reg cap (R1-proven pattern). Never LDC (rt floor 8), never in-loop LDS.
    float fv[25];
#pragma unroll
    for (int t = 0; t < 25; ++t) fv[t] = filt[t];

    // Rolling 5-row window: slot k%5 holds input row y0+k-2 (full unroll -> static)
    float W[5][8];
#pragma unroll
    for (int k = 0; k < 4; ++k)
        load_row8(W[k], ip, y0 + k - 2, x0, interior);

#pragma unroll
    for (int r = 0; r < RWS; ++r) {
        // Fresh row feeds tap row i=4 (consumed last) -> max latency slack
        load_row8(W[(r + 4) % 5], ip, y0 + r + 2, x0, interior);

        // Two interleaved min-chains per pixel (tap parity) -> 8 independent
        // FMNMX chains/thread, depth ~12 instead of ~24.
        float a0[XV], a1[XV];
#pragma unroll
        for (int t = 0; t < 25; ++t) {
            const int i = t / 5;
            const int j = t % 5;
            const float f = fv[t];
            const float* R = W[(r + i) % 5];     // input row y0+r+i-2
            if (t == 0) {
#pragma unroll
                for (int c = 0; c < XV; ++c) a0[c] = R[c + j] - f;
            } else if (t == 1) {
#pragma unroll
                for (int c = 0; c < XV; ++c) a1[c] = R[c + j] - f;
            } else if ((t & 1) == 0) {
#pragma unroll
                for (int c = 0; c < XV; ++c) a0[c] = fminf(a0[c], R[c + j] - f);
            } else {
#pragma unroll
                for (int c = 0; c < XV; ++c) a1[c] = fminf(a1[c], R[c + j] - f);
            }
        }

        float4 o;
        o.x = fminf(a0[0], a1[0]);
        o.y = fminf(a0[1], a1[1]);
        o.z = fminf(a0[2], a1[2]);
        o.w = fminf(a0[3], a1[3]);
        *reinterpret_cast<float4*>(op + (size_t)(y0 + r) * WW + x0) = o;
    }
}

extern "C" void kernel_launch(void* const* d_in, const int* in_sizes, int n_in,
                              void* d_out, int out_size) {
    const float* image = (const float*)d_in[0];
    const float* filt  = (const float*)d_in[1];
    float* out = (float*)d_out;

    const int planes = in_sizes[0] / (HH * WW);  // 32*3 = 96

    dim3 block(128, 1, 1);
    dim3 grid(WW / (128 * XV), HH / RWS, planes);  // (2, 64, 96)
    erosion5x5_f32v2_kernel<<<grid, block>>>(image, filt, out);
}

// round 7
// speedup vs baseline: 1.2733x; 1.1094x over previous
#include <cuda_runtime.h>
#include <cstdint>

#define HH 1024
#define WW 1024
#define XV 4      // output pixels per thread in x (one float4)
#define RWS 16    // output rows per thread strip

__device__ __forceinline__ void loadrow(float* wr, const float* __restrict__ ip,
                                        int y, int x0, bool interior_x, float INFv) {
    if (y < 0 || y >= HH) {
#pragma unroll
        for (int c = 0; c < 12; ++c) wr[c] = INFv;
    } else if (interior_x) {
        const float4* p = reinterpret_cast<const float4*>(ip + (size_t)y * WW + (x0 - 4));
        float4 a = p[0], b = p[1], c4 = p[2];
        wr[0] = a.x;  wr[1] = a.y;  wr[2] = a.z;  wr[3] = a.w;
        wr[4] = b.x;  wr[5] = b.y;  wr[6] = b.z;  wr[7] = b.w;
        wr[8] = c4.x; wr[9] = c4.y; wr[10] = c4.z; wr[11] = c4.w;
    } else {
#pragma unroll
        for (int c = 0; c < 12; ++c) {
            int col = x0 - 4 + c;
            wr[c] = (col >= 0 && col < WW) ? ip[(size_t)y * WW + col] : INFv;
        }
    }
}

__global__ __launch_bounds__(128)
void erosion5x5_tree_kernel(const float* __restrict__ img,
                            const float* __restrict__ filt,
                            float* __restrict__ out) {
    const int x0 = (blockIdx.x * blockDim.x + threadIdx.x) * XV;
    const int y0 = blockIdx.y * RWS;
    const size_t plane = (size_t)blockIdx.z * (size_t)HH * (size_t)WW;
    const float* ip = img + plane;
    float* op = out + plane;

    // Filter into registers (L1-hot loads, hoisted by full unroll) — as R1
    float fv[25];
#pragma unroll
    for (int t = 0; t < 25; ++t) fv[t] = filt[t];

    const float INFv = __int_as_float(0x7f800000);
    const bool interior_x = (x0 >= 4) && (x0 + 8 <= WW);

    // Rolling raw window: slot k%5 holds input row y0+k-2 — as R1
    float w[5][12];
#pragma unroll
    for (int k = 0; k < 4; ++k)
        loadrow(w[k], ip, y0 + k - 2, x0, interior_x, INFv);

#pragma unroll
    for (int r = 0; r < RWS; ++r) {
        // Bring in input row y0+r+2 (slot (r+4)%5) — as R1
        loadrow(w[(r + 4) % 5], ip, y0 + r + 2, x0, interior_x, INFv);

        // ONLY change vs R1: tree-shaped reduction.
        // Per SE-row i: 5 parallel subs -> 3-level min tree -> 1 acc link.
        // Chain depth per pixel ~9 levels instead of ~24 serial mins.
        float acc[XV];
#pragma unroll
        for (int i = 0; i < 5; ++i) {
            const float* R = w[(r + i) % 5];     // input row y0+r+i-2
            const float f0 = fv[i * 5 + 0];
            const float f1 = fv[i * 5 + 1];
            const float f2 = fv[i * 5 + 2];
            const float f3 = fv[i * 5 + 3];
            const float f4 = fv[i * 5 + 4];
#pragma unroll
            for (int c = 0; c < XV; ++c) {
                // w index: (x0+c+j-2) - (x0-4) = c + j + 2
                float s0 = R[c + 2] - f0;
                float s1 = R[c + 3] - f1;
                float s2 = R[c + 4] - f2;
                float s3 = R[c + 5] - f3;
                float s4 = R[c + 6] - f4;
                float m = fminf(fminf(fminf(s0, s1), fminf(s2, s3)), s4);
                acc[c] = (i == 0) ? m : fminf(acc[c], m);
            }
        }

        float4 o;
        o.x = acc[0]; o.y = acc[1]; o.z = acc[2]; o.w = acc[3];
        *reinterpret_cast<float4*>(op + (size_t)(y0 + r) * WW + x0) = o;
    }
}

extern "C" void kernel_launch(void* const* d_in, const int* in_sizes, int n_in,
                              void* d_out, int out_size) {
    const float* image = (const float*)d_in[0];
    const float* filt  = (const float*)d_in[1];
    float* out = (float*)d_out;

    const int planes = in_sizes[0] / (HH * WW);  // 32*3 = 96

    dim3 block(128, 1, 1);
    dim3 grid(WW / (128 * XV), HH / RWS, planes);  // (2, 64, 96)
    erosion5x5_tree_kernel<<<grid, block>>>(image, filt, out);
}